// round 2
// baseline (speedup 1.0000x reference)
#include <cuda_runtime.h>
#include <cuda_bf16.h>

#define NN   50000
#define MAXE 800000

// ---------------- scratch (static device globals; no allocation) ----------------
__device__ int   g_idx64;            // 1 if edge_index is int64, 0 if int32
__device__ int   g_deg[NN];
__device__ int   g_rowptr[NN + 1];
__device__ int   g_cursor[NN];
__device__ int   g_esrc[MAXE];
__device__ float g_dsinv[NN];
__device__ float g_feat[NN * 64];   // g = (h @ W) * dsinv[row]
__device__ float g_hbuf[NN * 64];   // layer output ping buffer

// ---------------- dtype probe ----------------
__global__ void detect_kernel(const void* __restrict__ ei, int E) {
    // One thread. If all sampled int64 reads are in-range, it's int64.
    const long long* p = (const long long*)ei;
    int ok = 1;
    for (int i = 0; i < 256; i++) {
        long long v = p[i];
        if (v < 0 || v >= NN) { ok = 0; break; }
    }
    if (ok) {
        for (int i = 0; i < 256; i++) {
            long long v = p[E + i];          // start of dst row (int64 layout)
            if (v < 0 || v >= NN) { ok = 0; break; }
        }
    }
    g_idx64 = ok;
}

__device__ __forceinline__ int load_idx(const void* ei, long long pos) {
    if (g_idx64) return (int)((const long long*)ei)[pos];
    return ((const int*)ei)[pos];
}

// ---------------- CSR build ----------------
__global__ void zero_deg_kernel() {
    int i = blockIdx.x * blockDim.x + threadIdx.x;
    if (i < NN) g_deg[i] = 0;
}

__global__ void hist_kernel(const void* __restrict__ ei, int E) {
    int e = blockIdx.x * blockDim.x + threadIdx.x;
    if (e < E) {
        int d = load_idx(ei, (long long)E + e);   // dst row
        if ((unsigned)d < (unsigned)NN) atomicAdd(&g_deg[d], 1);
    }
}

// single-block scan: rowptr (exclusive prefix of deg), cursor copy, dsinv = rsqrt(deg+1)
__global__ __launch_bounds__(1024) void scan_kernel() {
    const int T = 1024;
    const int CH = (NN + T - 1) / T;   // 49
    int t = threadIdx.x;
    int start = t * CH;
    int stop = min(start + CH, NN);

    int sum = 0;
    for (int i = start; i < stop; i++) sum += g_deg[i];

    int lane = t & 31, wid = t >> 5;
    const unsigned full = 0xffffffffu;
    int v = sum;
#pragma unroll
    for (int d = 1; d < 32; d <<= 1) {
        int n = __shfl_up_sync(full, v, d);
        if (lane >= d) v += n;
    }
    __shared__ int wsum[32];
    if (lane == 31) wsum[wid] = v;
    __syncthreads();
    if (wid == 0) {
        int wv = wsum[lane];
#pragma unroll
        for (int d = 1; d < 32; d <<= 1) {
            int n = __shfl_up_sync(full, wv, d);
            if (lane >= d) wv += n;
        }
        wsum[lane] = wv;
    }
    __syncthreads();
    int excl = v - sum + (wid ? wsum[wid - 1] : 0);

    int run = excl;
    for (int i = start; i < stop; i++) {
        int dg = g_deg[i];
        g_rowptr[i] = run;
        g_cursor[i] = run;
        g_dsinv[i] = rsqrtf((float)(dg + 1));   // +1 self loop; always > 0
        run += dg;
    }
    if (t == T - 1) g_rowptr[NN] = run;
}

__global__ void scatter_kernel(const void* __restrict__ ei, int E) {
    int e = blockIdx.x * blockDim.x + threadIdx.x;
    if (e < E) {
        int s = load_idx(ei, e);                  // src row
        int d = load_idx(ei, (long long)E + e);   // dst row
        if ((unsigned)d < (unsigned)NN && (unsigned)s < (unsigned)NN) {
            int p = atomicAdd(&g_cursor[d], 1);
            if ((unsigned)p < (unsigned)MAXE) g_esrc[p] = s;
        }
    }
}

// ---------------- fused GEMM (g = A@W scaled by dsinv[row]) ----------------
// block = 256 threads computes a 64-row x 64-col tile; 4x4 microtile per thread.
__global__ __launch_bounds__(256) void gemm_scale_kernel(const float* __restrict__ Ain,
                                                         const float* __restrict__ W,
                                                         int use_hbuf) {
    __shared__ float sAT[64][68];      // [k][row], padded (272B rows keep 16B align)
    __shared__ float sW[64 * 64];      // [k][j]
    const float* A = use_hbuf ? g_hbuf : Ain;

    int t = threadIdx.x;
    int row0 = blockIdx.x * 64;

    {
        const float4* W4 = (const float4*)W;
        float4* sW4 = (float4*)sW;
#pragma unroll
        for (int i = 0; i < 4; i++) sW4[t + i * 256] = W4[t + i * 256];
    }
#pragma unroll
    for (int i = 0; i < 4; i++) {
        int q = t + i * 256;           // float4 index within tile (0..1023)
        int r = q >> 4;                // row 0..63
        int k = (q & 15) << 2;         // k 0,4,..,60
        float4 v = make_float4(0.f, 0.f, 0.f, 0.f);
        int grow = row0 + r;
        if (grow < NN) v = *(const float4*)(A + grow * 64 + k);
        sAT[k + 0][r] = v.x; sAT[k + 1][r] = v.y;
        sAT[k + 2][r] = v.z; sAT[k + 3][r] = v.w;
    }
    __syncthreads();

    int tx = t & 15, ty = t >> 4;
    float acc[4][4];
#pragma unroll
    for (int r = 0; r < 4; r++)
#pragma unroll
        for (int c = 0; c < 4; c++) acc[r][c] = 0.f;

#pragma unroll
    for (int k = 0; k < 64; k++) {
        float4 a = *(const float4*)(&sAT[k][ty << 2]);
        float4 b = *(const float4*)(&sW[k * 64 + (tx << 2)]);
        acc[0][0] += a.x * b.x; acc[0][1] += a.x * b.y; acc[0][2] += a.x * b.z; acc[0][3] += a.x * b.w;
        acc[1][0] += a.y * b.x; acc[1][1] += a.y * b.y; acc[1][2] += a.y * b.z; acc[1][3] += a.y * b.w;
        acc[2][0] += a.z * b.x; acc[2][1] += a.z * b.y; acc[2][2] += a.z * b.z; acc[2][3] += a.z * b.w;
        acc[3][0] += a.w * b.x; acc[3][1] += a.w * b.y; acc[3][2] += a.w * b.z; acc[3][3] += a.w * b.w;
    }

#pragma unroll
    for (int r = 0; r < 4; r++) {
        int grow = row0 + (ty << 2) + r;
        if (grow < NN) {
            float s = g_dsinv[grow];
            float4 o = make_float4(acc[r][0] * s, acc[r][1] * s,
                                   acc[r][2] * s, acc[r][3] * s);
            *(float4*)(g_feat + grow * 64 + (tx << 2)) = o;
        }
    }
}

// ---------------- aggregation: one warp per node, CSR gather ----------------
// out[d] = dsinv[d] * (g[d] + sum_{e:dst=d} g[src_e]) + bias ; relu for mode<2
__global__ __launch_bounds__(256) void aggregate_kernel(const float* __restrict__ bias,
                                                        float* __restrict__ dout,
                                                        int mode) {
    int warp = (blockIdx.x * blockDim.x + threadIdx.x) >> 5;
    int lane = threadIdx.x & 31;
    if (warp >= NN) return;
    int node = warp;
    int beg = g_rowptr[node];
    int end = g_rowptr[node + 1];

    const float2* Gv = (const float2*)g_feat;
    int off = node * 32 + lane;
    float2 s0v = Gv[off];             // self-loop term g[node]
    float ax = s0v.x, ay = s0v.y;

    const unsigned full = 0xffffffffu;
    for (int base = beg; base < end; base += 32) {
        int idx = base + lane;
        int mysrc = (idx < end) ? g_esrc[idx] : 0;
        int cnt = min(32, end - base);
        int i = 0;
        for (; i + 4 <= cnt; i += 4) {
            int s0 = __shfl_sync(full, mysrc, i);
            int s1 = __shfl_sync(full, mysrc, i + 1);
            int s2 = __shfl_sync(full, mysrc, i + 2);
            int s3 = __shfl_sync(full, mysrc, i + 3);
            float2 v0 = Gv[s0 * 32 + lane];
            float2 v1 = Gv[s1 * 32 + lane];
            float2 v2 = Gv[s2 * 32 + lane];
            float2 v3 = Gv[s3 * 32 + lane];
            ax += v0.x; ay += v0.y;
            ax += v1.x; ay += v1.y;
            ax += v2.x; ay += v2.y;
            ax += v3.x; ay += v3.y;
        }
        for (; i < cnt; i++) {
            int s = __shfl_sync(full, mysrc, i);
            float2 v = Gv[s * 32 + lane];
            ax += v.x; ay += v.y;
        }
    }

    float ds = g_dsinv[node];
    float o0 = fmaf(ds, ax, bias[lane * 2]);
    float o1 = fmaf(ds, ay, bias[lane * 2 + 1]);
    float2* outv;
    if (mode < 2) {
        o0 = fmaxf(o0, 0.f);
        o1 = fmaxf(o1, 0.f);
        outv = (float2*)g_hbuf;
    } else {
        outv = (float2*)dout;
    }
    outv[off] = make_float2(o0, o1);
}

// ---------------- launch ----------------
extern "C" void kernel_launch(void* const* d_in, const int* in_sizes, int n_in,
                              void* d_out, int out_size) {
    const float* x  = (const float*)d_in[0];
    const void*  ei = d_in[1];
    const float* W0 = (const float*)d_in[2];
    const float* b0 = (const float*)d_in[3];
    const float* W1 = (const float*)d_in[4];
    const float* b1 = (const float*)d_in[5];
    const float* W2 = (const float*)d_in[6];
    const float* b2 = (const float*)d_in[7];
    float* out = (float*)d_out;

    int E = in_sizes[1] / 2;

    // dtype probe + CSR build (recomputed every call; deterministic work)
    detect_kernel<<<1, 1>>>(ei, E);
    zero_deg_kernel<<<(NN + 255) / 256, 256>>>();
    hist_kernel<<<(E + 255) / 256, 256>>>(ei, E);
    scan_kernel<<<1, 1024>>>();
    scatter_kernel<<<(E + 255) / 256, 256>>>(ei, E);

    int gemm_blocks = (NN + 63) / 64;
    int agg_blocks  = (NN * 32 + 255) / 256;

    // layer 0
    gemm_scale_kernel<<<gemm_blocks, 256>>>(x, W0, 0);
    aggregate_kernel<<<agg_blocks, 256>>>(b0, out, 0);
    // layer 1
    gemm_scale_kernel<<<gemm_blocks, 256>>>(x, W1, 1);
    aggregate_kernel<<<agg_blocks, 256>>>(b1, out, 1);
    // layer 2 (no relu, write d_out)
    gemm_scale_kernel<<<gemm_blocks, 256>>>(x, W2, 1);
    aggregate_kernel<<<agg_blocks, 256>>>(b2, out, 2);
}

// round 3
// speedup vs baseline: 1.7715x; 1.7715x over previous
#include <cuda_runtime.h>
#include <cuda_bf16.h>

#define NN   50000
#define MAXE 800000
#define NB   196            // ceil(NN/256)

// ---------------- scratch (static device globals; no allocation) ----------------
__device__ int   g_idx64;           // 1 if edge_index is int64, 0 if int32
__device__ int   g_deg[NN];
__device__ int   g_rowptr[NN + 1];
__device__ int   g_cursor[NN];
__device__ int   g_esrc[MAXE];
__device__ int   g_bsum[NB];
__device__ int   g_boff[NB];
__device__ float g_dsinv[NN];
__device__ float g_feat[NN * 64];   // g = (h @ W) * dsinv[row]
__device__ float g_hbuf[NN * 64];   // layer output ping buffer

// ---------------- dtype probe (parallel, branch-free loads) ----------------
__global__ void detect_kernel(const void* __restrict__ ei, int E) {
    __shared__ int bad;
    if (threadIdx.x == 0) bad = 0;
    __syncthreads();
    const long long* p = (const long long*)ei;
    long long v1 = p[threadIdx.x];
    long long v2 = p[E + threadIdx.x];
    if (v1 < 0 || v1 >= NN || v2 < 0 || v2 >= NN) bad = 1;
    __syncthreads();
    if (threadIdx.x == 0) g_idx64 = !bad;
}

__device__ __forceinline__ int load_idx(const void* ei, long long pos) {
    if (g_idx64) return (int)((const long long*)ei)[pos];
    return ((const int*)ei)[pos];
}

// ---------------- CSR build ----------------
__global__ void zero_deg_kernel() {
    int i = blockIdx.x * blockDim.x + threadIdx.x;
    if (i < NN) g_deg[i] = 0;
}

__global__ void hist_kernel(const void* __restrict__ ei, int E) {
    int e = blockIdx.x * blockDim.x + threadIdx.x;
    if (e < E) {
        int d = load_idx(ei, (long long)E + e);   // dst row
        if ((unsigned)d < (unsigned)NN) atomicAdd(&g_deg[d], 1);
    }
}

// inclusive scan across a 256-thread block; sh_warp must hold >= 8 ints
__device__ __forceinline__ int block_incl_scan(int v, int* sh_warp) {
    const unsigned full = 0xffffffffu;
    int lane = threadIdx.x & 31, wid = threadIdx.x >> 5;
    int x = v;
#pragma unroll
    for (int d = 1; d < 32; d <<= 1) {
        int n = __shfl_up_sync(full, x, d);
        if (lane >= d) x += n;
    }
    if (lane == 31) sh_warp[wid] = x;
    __syncthreads();
    if (wid == 0) {
        int w = (lane < 8) ? sh_warp[lane] : 0;
#pragma unroll
        for (int d = 1; d < 8; d <<= 1) {
            int n = __shfl_up_sync(full, w, d);
            if (lane >= d) w += n;
        }
        if (lane < 8) sh_warp[lane] = w;
    }
    __syncthreads();
    return x + (wid ? sh_warp[wid - 1] : 0);
}

// stage 1: per-block sums of deg
__global__ __launch_bounds__(256) void partial_kernel() {
    __shared__ int sh[8];
    int t = threadIdx.x;
    int i = blockIdx.x * 256 + t;
    int v = (i < NN) ? g_deg[i] : 0;
    int ws = __reduce_add_sync(0xffffffffu, v);
    if ((t & 31) == 0) sh[t >> 5] = ws;
    __syncthreads();
    if (t == 0) {
        int s = 0;
#pragma unroll
        for (int w = 0; w < 8; w++) s += sh[w];
        g_bsum[blockIdx.x] = s;
    }
}

// stage 2: exclusive scan of the NB block sums (single small block)
__global__ __launch_bounds__(256) void bsum_scan_kernel() {
    __shared__ int sh[8];
    int t = threadIdx.x;
    int v = (t < NB) ? g_bsum[t] : 0;
    int incl = block_incl_scan(v, sh);
    if (t < NB) g_boff[t] = incl - v;
}

// stage 3: per-block local scan + offset; write rowptr/cursor/dsinv
__global__ __launch_bounds__(256) void fill_kernel() {
    __shared__ int sh[8];
    int t = threadIdx.x;
    int i = blockIdx.x * 256 + t;
    int v = (i < NN) ? g_deg[i] : 0;
    int incl = block_incl_scan(v, sh);
    int base = g_boff[blockIdx.x];
    if (i < NN) {
        int excl = base + incl - v;
        g_rowptr[i] = excl;
        g_cursor[i] = excl;
        g_dsinv[i]  = rsqrtf((float)(v + 1));   // +1 self loop
        if (i == NN - 1) g_rowptr[NN] = base + incl;
    }
}

__global__ void scatter_kernel(const void* __restrict__ ei, int E) {
    int e = blockIdx.x * blockDim.x + threadIdx.x;
    if (e < E) {
        int s = load_idx(ei, e);                  // src row
        int d = load_idx(ei, (long long)E + e);   // dst row
        if ((unsigned)d < (unsigned)NN && (unsigned)s < (unsigned)NN) {
            int p = atomicAdd(&g_cursor[d], 1);
            if ((unsigned)p < (unsigned)MAXE) g_esrc[p] = s;
        }
    }
}

// ---------------- fused GEMM (g = A@W scaled by dsinv[row]) ----------------
// block = 256 threads computes a 64-row x 64-col tile; 4x4 microtile per thread.
__global__ __launch_bounds__(256) void gemm_scale_kernel(const float* __restrict__ Ain,
                                                         const float* __restrict__ W,
                                                         int use_hbuf) {
    __shared__ float sAT[64][68];      // [k][row], padded
    __shared__ float sW[64 * 64];      // [k][j]
    const float* A = use_hbuf ? g_hbuf : Ain;

    int t = threadIdx.x;
    int row0 = blockIdx.x * 64;

    {
        const float4* W4 = (const float4*)W;
        float4* sW4 = (float4*)sW;
#pragma unroll
        for (int i = 0; i < 4; i++) sW4[t + i * 256] = W4[t + i * 256];
    }
#pragma unroll
    for (int i = 0; i < 4; i++) {
        int q = t + i * 256;           // float4 index within tile (0..1023)
        int r = q >> 4;                // row 0..63
        int k = (q & 15) << 2;         // k 0,4,..,60
        float4 v = make_float4(0.f, 0.f, 0.f, 0.f);
        int grow = row0 + r;
        if (grow < NN) v = *(const float4*)(A + grow * 64 + k);
        sAT[k + 0][r] = v.x; sAT[k + 1][r] = v.y;
        sAT[k + 2][r] = v.z; sAT[k + 3][r] = v.w;
    }
    __syncthreads();

    int tx = t & 15, ty = t >> 4;
    float acc[4][4];
#pragma unroll
    for (int r = 0; r < 4; r++)
#pragma unroll
        for (int c = 0; c < 4; c++) acc[r][c] = 0.f;

#pragma unroll
    for (int k = 0; k < 64; k++) {
        float4 a = *(const float4*)(&sAT[k][ty << 2]);
        float4 b = *(const float4*)(&sW[k * 64 + (tx << 2)]);
        acc[0][0] += a.x * b.x; acc[0][1] += a.x * b.y; acc[0][2] += a.x * b.z; acc[0][3] += a.x * b.w;
        acc[1][0] += a.y * b.x; acc[1][1] += a.y * b.y; acc[1][2] += a.y * b.z; acc[1][3] += a.y * b.w;
        acc[2][0] += a.z * b.x; acc[2][1] += a.z * b.y; acc[2][2] += a.z * b.z; acc[2][3] += a.z * b.w;
        acc[3][0] += a.w * b.x; acc[3][1] += a.w * b.y; acc[3][2] += a.w * b.z; acc[3][3] += a.w * b.w;
    }

#pragma unroll
    for (int r = 0; r < 4; r++) {
        int grow = row0 + (ty << 2) + r;
        if (grow < NN) {
            float s = g_dsinv[grow];
            float4 o = make_float4(acc[r][0] * s, acc[r][1] * s,
                                   acc[r][2] * s, acc[r][3] * s);
            *(float4*)(g_feat + grow * 64 + (tx << 2)) = o;
        }
    }
}

// ---------------- aggregation: one warp per node, CSR gather ----------------
// out[d] = dsinv[d] * (g[d] + sum_{e:dst=d} g[src_e]) + bias ; relu for mode<2
__global__ __launch_bounds__(256) void aggregate_kernel(const float* __restrict__ bias,
                                                        float* __restrict__ dout,
                                                        int mode) {
    int warp = (blockIdx.x * blockDim.x + threadIdx.x) >> 5;
    int lane = threadIdx.x & 31;
    if (warp >= NN) return;
    int node = warp;
    int beg = g_rowptr[node];
    int end = g_rowptr[node + 1];

    const float2* Gv = (const float2*)g_feat;
    int off = node * 32 + lane;
    float2 s0v = Gv[off];             // self-loop term g[node]
    float ax = s0v.x, ay = s0v.y;

    const unsigned full = 0xffffffffu;
    for (int base = beg; base < end; base += 32) {
        int idx = base + lane;
        int mysrc = (idx < end) ? g_esrc[idx] : 0;
        int cnt = min(32, end - base);
        int i = 0;
        for (; i + 4 <= cnt; i += 4) {
            int s0 = __shfl_sync(full, mysrc, i);
            int s1 = __shfl_sync(full, mysrc, i + 1);
            int s2 = __shfl_sync(full, mysrc, i + 2);
            int s3 = __shfl_sync(full, mysrc, i + 3);
            float2 v0 = Gv[s0 * 32 + lane];
            float2 v1 = Gv[s1 * 32 + lane];
            float2 v2 = Gv[s2 * 32 + lane];
            float2 v3 = Gv[s3 * 32 + lane];
            ax += v0.x; ay += v0.y;
            ax += v1.x; ay += v1.y;
            ax += v2.x; ay += v2.y;
            ax += v3.x; ay += v3.y;
        }
        for (; i < cnt; i++) {
            int s = __shfl_sync(full, mysrc, i);
            float2 v = Gv[s * 32 + lane];
            ax += v.x; ay += v.y;
        }
    }

    float ds = g_dsinv[node];
    float o0 = fmaf(ds, ax, bias[lane * 2]);
    float o1 = fmaf(ds, ay, bias[lane * 2 + 1]);
    float2* outv;
    if (mode < 2) {
        o0 = fmaxf(o0, 0.f);
        o1 = fmaxf(o1, 0.f);
        outv = (float2*)g_hbuf;
    } else {
        outv = (float2*)dout;
    }
    outv[off] = make_float2(o0, o1);
}

// ---------------- launch ----------------
extern "C" void kernel_launch(void* const* d_in, const int* in_sizes, int n_in,
                              void* d_out, int out_size) {
    const float* x  = (const float*)d_in[0];
    const void*  ei = d_in[1];
    const float* W0 = (const float*)d_in[2];
    const float* b0 = (const float*)d_in[3];
    const float* W1 = (const float*)d_in[4];
    const float* b1 = (const float*)d_in[5];
    const float* W2 = (const float*)d_in[6];
    const float* b2 = (const float*)d_in[7];
    float* out = (float*)d_out;

    int E = in_sizes[1] / 2;

    // dtype probe + CSR build (recomputed every call; deterministic work)
    detect_kernel<<<1, 256>>>(ei, E);
    zero_deg_kernel<<<(NN + 255) / 256, 256>>>();
    hist_kernel<<<(E + 255) / 256, 256>>>(ei, E);
    partial_kernel<<<NB, 256>>>();
    bsum_scan_kernel<<<1, 256>>>();
    fill_kernel<<<NB, 256>>>();
    scatter_kernel<<<(E + 255) / 256, 256>>>(ei, E);

    int gemm_blocks = (NN + 63) / 64;
    int agg_blocks  = (NN * 32 + 255) / 256;

    // layer 0
    gemm_scale_kernel<<<gemm_blocks, 256>>>(x, W0, 0);
    aggregate_kernel<<<agg_blocks, 256>>>(b0, out, 0);
    // layer 1
    gemm_scale_kernel<<<gemm_blocks, 256>>>(x, W1, 1);
    aggregate_kernel<<<agg_blocks, 256>>>(b1, out, 1);
    // layer 2 (no relu, write d_out)
    gemm_scale_kernel<<<gemm_blocks, 256>>>(x, W2, 1);
    aggregate_kernel<<<agg_blocks, 256>>>(b2, out, 2);
}

// round 5
// speedup vs baseline: 1.7787x; 1.0040x over previous
#include <cuda_runtime.h>
#include <cuda_bf16.h>

#define NN   50000
#define MAXE 800000
#define NB   196            // ceil(NN/256)

// ---------------- scratch (static device globals; no allocation) ----------------
__device__ int      g_deg[NN];          // zero-initialized at load; re-zeroed by scan each call
__device__ int      g_rowptr[NN + 1];
__device__ int      g_cursor[NN];
__device__ int      g_esrc[MAXE];
__device__ unsigned g_bstate[NB];       // lookback state: [31:30]=flag (1=agg,2=prefix), [29:0]=sum
__device__ float    g_dsinv[NN];
__device__ float    g_feat[NN * 64];    // g = (h @ W) * dsinv[row]
__device__ float    g_hbuf[NN * 64];    // layer output ping buffer

// per-block dtype consensus: read first 256 int64 slots (in-bounds for BOTH layouts)
__device__ __forceinline__ int block_detect_i64(const void* ei) {
    long long v = ((const long long*)ei)[threadIdx.x & 255];
    return __syncthreads_and(v >= 0 && v < NN);
}

// ---------------- hist: deg histogram (+ lookback-state reset by block 0) ----------------
__global__ __launch_bounds__(256) void hist_kernel(const void* __restrict__ ei, int E) {
    int is64 = block_detect_i64(ei);
    if (blockIdx.x == 0 && threadIdx.x < NB) g_bstate[threadIdx.x] = 0u;
    int e = blockIdx.x * 256 + threadIdx.x;
    if (e < E) {
        int d = is64 ? (int)((const long long*)ei)[(long long)E + e]
                     : ((const int*)ei)[(long long)E + e];
        if ((unsigned)d < (unsigned)NN) atomicAdd(&g_deg[d], 1);
    }
}

// ---------------- single-kernel decoupled-lookback scan ----------------
// writes rowptr/cursor/dsinv; re-zeroes deg after reading it.
__global__ __launch_bounds__(256) void scan_kernel() {
    const unsigned full = 0xffffffffu;
    __shared__ int sh[8];
    __shared__ int s_prefix;
    int b = blockIdx.x, t = threadIdx.x;
    int lane = t & 31, wid = t >> 5;
    int i = b * 256 + t;

    int v = (i < NN) ? g_deg[i] : 0;

    // block inclusive scan
    int x = v;
#pragma unroll
    for (int d = 1; d < 32; d <<= 1) {
        int n = __shfl_up_sync(full, x, d);
        if (lane >= d) x += n;
    }
    if (lane == 31) sh[wid] = x;
    __syncthreads();
    if (wid == 0) {
        int w = (lane < 8) ? sh[lane] : 0;
#pragma unroll
        for (int d = 1; d < 8; d <<= 1) {
            int n = __shfl_up_sync(full, w, d);
            if (lane >= d) w += n;
        }
        if (lane < 8) sh[lane] = w;
    }
    __syncthreads();
    int incl = x + (wid ? sh[wid - 1] : 0);
    int S = sh[7];                       // block total

    // publish aggregate early (single word carries flag+value: no fence needed)
    if (t == 0 && b > 0) atomicExch((int*)&g_bstate[b], (1 << 30) | S);

    // lookback (warp 0)
    if (wid == 0) {
        int running = 0;
        if (b > 0) {
            int idx = b - 1;
            while (true) {
                int j = idx - lane;
                unsigned st;
                do {
                    st = (j >= 0) ? (unsigned)atomicAdd((int*)&g_bstate[j], 0)
                                  : (2u << 30);
                } while (__any_sync(full, (st >> 30) == 0));
                int val = (int)(st & 0x3FFFFFFF);
                unsigned pm = __ballot_sync(full, (st >> 30) == 2u);
                if (pm) {
                    int firstP = __ffs(pm) - 1;          // closest prefix to idx
                    int contrib = (lane <= firstP) ? val : 0;
#pragma unroll
                    for (int d = 16; d; d >>= 1) contrib += __shfl_down_sync(full, contrib, d);
                    running += __shfl_sync(full, contrib, 0);
                    break;
                } else {
                    int contrib = val;
#pragma unroll
                    for (int d = 16; d; d >>= 1) contrib += __shfl_down_sync(full, contrib, d);
                    running += __shfl_sync(full, contrib, 0);
                    idx -= 32;
                }
            }
        }
        if (lane == 0) {
            atomicExch((int*)&g_bstate[b], (2 << 30) | (running + S));
            s_prefix = running;
        }
    }
    __syncthreads();

    if (i < NN) {
        int excl = s_prefix + incl - v;
        g_rowptr[i] = excl;
        g_cursor[i] = excl;
        g_dsinv[i]  = rsqrtf((float)(v + 1));   // +1 self loop
        g_deg[i]    = 0;                        // restore invariant for next call
        if (i == NN - 1) g_rowptr[NN] = s_prefix + incl;
    }
}

// ---------------- scatter: fill CSR adjacency ----------------
__global__ __launch_bounds__(256) void scatter_kernel(const void* __restrict__ ei, int E) {
    int is64 = block_detect_i64(ei);
    int e = blockIdx.x * 256 + threadIdx.x;
    if (e < E) {
        int s, d;
        if (is64) {
            s = (int)((const long long*)ei)[e];
            d = (int)((const long long*)ei)[(long long)E + e];
        } else {
            s = ((const int*)ei)[e];
            d = ((const int*)ei)[(long long)E + e];
        }
        if ((unsigned)d < (unsigned)NN && (unsigned)s < (unsigned)NN) {
            int p = atomicAdd(&g_cursor[d], 1);
            if ((unsigned)p < (unsigned)MAXE) g_esrc[p] = s;
        }
    }
}

// ---------------- fused GEMM (g = A@W scaled by dsinv[row]) ----------------
__global__ __launch_bounds__(256) void gemm_scale_kernel(const float* __restrict__ Ain,
                                                         const float* __restrict__ W,
                                                         int use_hbuf) {
    __shared__ float sAT[64][68];
    __shared__ float sW[64 * 64];
    const float* A = use_hbuf ? g_hbuf : Ain;

    int t = threadIdx.x;
    int row0 = blockIdx.x * 64;

    {
        const float4* W4 = (const float4*)W;
        float4* sW4 = (float4*)sW;
#pragma unroll
        for (int i = 0; i < 4; i++) sW4[t + i * 256] = W4[t + i * 256];
    }
#pragma unroll
    for (int i = 0; i < 4; i++) {
        int q = t + i * 256;
        int r = q >> 4;
        int k = (q & 15) << 2;
        float4 v = make_float4(0.f, 0.f, 0.f, 0.f);
        int grow = row0 + r;
        if (grow < NN) v = *(const float4*)(A + grow * 64 + k);
        sAT[k + 0][r] = v.x; sAT[k + 1][r] = v.y;
        sAT[k + 2][r] = v.z; sAT[k + 3][r] = v.w;
    }
    __syncthreads();

    int tx = t & 15, ty = t >> 4;
    float acc[4][4];
#pragma unroll
    for (int r = 0; r < 4; r++)
#pragma unroll
        for (int c = 0; c < 4; c++) acc[r][c] = 0.f;

#pragma unroll
    for (int k = 0; k < 64; k++) {
        float4 a = *(const float4*)(&sAT[k][ty << 2]);
        float4 b = *(const float4*)(&sW[k * 64 + (tx << 2)]);
        acc[0][0] += a.x * b.x; acc[0][1] += a.x * b.y; acc[0][2] += a.x * b.z; acc[0][3] += a.x * b.w;
        acc[1][0] += a.y * b.x; acc[1][1] += a.y * b.y; acc[1][2] += a.y * b.z; acc[1][3] += a.y * b.w;
        acc[2][0] += a.z * b.x; acc[2][1] += a.z * b.y; acc[2][2] += a.z * b.z; acc[2][3] += a.z * b.w;
        acc[3][0] += a.w * b.x; acc[3][1] += a.w * b.y; acc[3][2] += a.w * b.z; acc[3][3] += a.w * b.w;
    }

#pragma unroll
    for (int r = 0; r < 4; r++) {
        int grow = row0 + (ty << 2) + r;
        if (grow < NN) {
            float s = g_dsinv[grow];
            float4 o = make_float4(acc[r][0] * s, acc[r][1] * s,
                                   acc[r][2] * s, acc[r][3] * s);
            *(float4*)(g_feat + grow * 64 + (tx << 2)) = o;
        }
    }
}

// ---------------- aggregation: one warp per node, CSR gather, 8-deep MLP ----------------
__global__ __launch_bounds__(256) void aggregate_kernel(const float* __restrict__ bias,
                                                        float* __restrict__ dout,
                                                        int mode) {
    int warp = (blockIdx.x * blockDim.x + threadIdx.x) >> 5;
    int lane = threadIdx.x & 31;
    if (warp >= NN) return;
    int node = warp;
    int beg = g_rowptr[node];
    int end = g_rowptr[node + 1];

    const float2* __restrict__ Gv = (const float2*)g_feat;
    int off = node * 32 + lane;
    float2 s0v = Gv[off];             // self-loop term g[node]
    float ax = s0v.x, ay = s0v.y;

    const unsigned full = 0xffffffffu;
    for (int base = beg; base < end; base += 32) {
        int idx = base + lane;
        int mysrc = (idx < end) ? g_esrc[idx] : 0;
        int cnt = min(32, end - base);
        int i = 0;
        for (; i + 8 <= cnt; i += 8) {
            int s0 = __shfl_sync(full, mysrc, i);
            int s1 = __shfl_sync(full, mysrc, i + 1);
            int s2 = __shfl_sync(full, mysrc, i + 2);
            int s3 = __shfl_sync(full, mysrc, i + 3);
            int s4 = __shfl_sync(full, mysrc, i + 4);
            int s5 = __shfl_sync(full, mysrc, i + 5);
            int s6 = __shfl_sync(full, mysrc, i + 6);
            int s7 = __shfl_sync(full, mysrc, i + 7);
            float2 v0 = Gv[s0 * 32 + lane];
            float2 v1 = Gv[s1 * 32 + lane];
            float2 v2 = Gv[s2 * 32 + lane];
            float2 v3 = Gv[s3 * 32 + lane];
            float2 v4 = Gv[s4 * 32 + lane];
            float2 v5 = Gv[s5 * 32 + lane];
            float2 v6 = Gv[s6 * 32 + lane];
            float2 v7 = Gv[s7 * 32 + lane];
            ax += v0.x; ay += v0.y; ax += v1.x; ay += v1.y;
            ax += v2.x; ay += v2.y; ax += v3.x; ay += v3.y;
            ax += v4.x; ay += v4.y; ax += v5.x; ay += v5.y;
            ax += v6.x; ay += v6.y; ax += v7.x; ay += v7.y;
        }
        for (; i < cnt; i++) {
            int s = __shfl_sync(full, mysrc, i);
            float2 v = Gv[s * 32 + lane];
            ax += v.x; ay += v.y;
        }
    }

    float ds = g_dsinv[node];
    float o0 = fmaf(ds, ax, bias[lane * 2]);
    float o1 = fmaf(ds, ay, bias[lane * 2 + 1]);
    float2* outv;
    if (mode < 2) {
        o0 = fmaxf(o0, 0.f);
        o1 = fmaxf(o1, 0.f);
        outv = (float2*)g_hbuf;
    } else {
        outv = (float2*)dout;
    }
    outv[off] = make_float2(o0, o1);
}

// ---------------- launch ----------------
extern "C" void kernel_launch(void* const* d_in, const int* in_sizes, int n_in,
                              void* d_out, int out_size) {
    const float* x  = (const float*)d_in[0];
    const void*  ei = d_in[1];
    const float* W0 = (const float*)d_in[2];
    const float* b0 = (const float*)d_in[3];
    const float* W1 = (const float*)d_in[4];
    const float* b1 = (const float*)d_in[5];
    const float* W2 = (const float*)d_in[6];
    const float* b2 = (const float*)d_in[7];
    float* out = (float*)d_out;

    int E = in_sizes[1] / 2;

    hist_kernel<<<(E + 255) / 256, 256>>>(ei, E);
    scan_kernel<<<NB, 256>>>();
    scatter_kernel<<<(E + 255) / 256, 256>>>(ei, E);

    int gemm_blocks = (NN + 63) / 64;
    int agg_blocks  = (NN * 32 + 255) / 256;

    gemm_scale_kernel<<<gemm_blocks, 256>>>(x, W0, 0);   // launch #4 → profiled
    aggregate_kernel<<<agg_blocks, 256>>>(b0, out, 0);
    gemm_scale_kernel<<<gemm_blocks, 256>>>(x, W1, 1);
    aggregate_kernel<<<agg_blocks, 256>>>(b1, out, 1);
    gemm_scale_kernel<<<gemm_blocks, 256>>>(x, W2, 1);
    aggregate_kernel<<<agg_blocks, 256>>>(b2, out, 2);
}

// round 7
// speedup vs baseline: 1.8299x; 1.0288x over previous
#include <cuda_runtime.h>
#include <cuda_bf16.h>
#include <cstdint>

#define NN   50000
#define MAXE 800000
#define NB   196            // ceil(NN/256)

// ---------------- scratch (static device globals; no allocation) ----------------
__device__ int      g_deg[NN];          // zero-initialized at load; re-zeroed by scan each call
__device__ int      g_rowptr[NN + 1];
__device__ int      g_cursor[NN];
__device__ int      g_esrc[MAXE];
__device__ unsigned g_bstate[NB];       // lookback state: [31:30]=flag (1=agg,2=prefix), [29:0]=sum
__device__ float    g_dsinv[NN];
__device__ float    g_feat[NN * 64];    // g = (h @ W) * dsinv[row]
__device__ float    g_hbuf[NN * 64];    // layer output ping buffer

// per-block dtype consensus: read first 256 int64 slots (in-bounds for BOTH layouts)
__device__ __forceinline__ int block_detect_i64(const void* ei) {
    long long v = ((const long long*)ei)[threadIdx.x & 255];
    return __syncthreads_and(v >= 0 && v < NN);
}

// ---------------- hist: deg histogram (+ lookback-state reset by block 0) ----------------
__global__ __launch_bounds__(256) void hist_kernel(const void* __restrict__ ei, int E) {
    int is64 = block_detect_i64(ei);
    if (blockIdx.x == 0 && threadIdx.x < NB) g_bstate[threadIdx.x] = 0u;
    int e = blockIdx.x * 256 + threadIdx.x;
    if (e < E) {
        int d = is64 ? (int)((const long long*)ei)[(long long)E + e]
                     : ((const int*)ei)[(long long)E + e];
        if ((unsigned)d < (unsigned)NN) atomicAdd(&g_deg[d], 1);
    }
}

// ---------------- single-kernel decoupled-lookback scan ----------------
__global__ __launch_bounds__(256) void scan_kernel() {
    const unsigned full = 0xffffffffu;
    __shared__ int sh[8];
    __shared__ int s_prefix;
    int b = blockIdx.x, t = threadIdx.x;
    int lane = t & 31, wid = t >> 5;
    int i = b * 256 + t;

    int v = (i < NN) ? g_deg[i] : 0;

    int x = v;
#pragma unroll
    for (int d = 1; d < 32; d <<= 1) {
        int n = __shfl_up_sync(full, x, d);
        if (lane >= d) x += n;
    }
    if (lane == 31) sh[wid] = x;
    __syncthreads();
    if (wid == 0) {
        int w = (lane < 8) ? sh[lane] : 0;
#pragma unroll
        for (int d = 1; d < 8; d <<= 1) {
            int n = __shfl_up_sync(full, w, d);
            if (lane >= d) w += n;
        }
        if (lane < 8) sh[lane] = w;
    }
    __syncthreads();
    int incl = x + (wid ? sh[wid - 1] : 0);
    int S = sh[7];

    if (t == 0 && b > 0) atomicExch((int*)&g_bstate[b], (1 << 30) | S);

    if (wid == 0) {
        int running = 0;
        if (b > 0) {
            int idx = b - 1;
            while (true) {
                int j = idx - lane;
                unsigned st;
                do {
                    st = (j >= 0) ? (unsigned)atomicAdd((int*)&g_bstate[j], 0)
                                  : (2u << 30);
                } while (__any_sync(full, (st >> 30) == 0));
                int val = (int)(st & 0x3FFFFFFF);
                unsigned pm = __ballot_sync(full, (st >> 30) == 2u);
                if (pm) {
                    int firstP = __ffs(pm) - 1;
                    int contrib = (lane <= firstP) ? val : 0;
#pragma unroll
                    for (int d = 16; d; d >>= 1) contrib += __shfl_down_sync(full, contrib, d);
                    running += __shfl_sync(full, contrib, 0);
                    break;
                } else {
                    int contrib = val;
#pragma unroll
                    for (int d = 16; d; d >>= 1) contrib += __shfl_down_sync(full, contrib, d);
                    running += __shfl_sync(full, contrib, 0);
                    idx -= 32;
                }
            }
        }
        if (lane == 0) {
            atomicExch((int*)&g_bstate[b], (2 << 30) | (running + S));
            s_prefix = running;
        }
    }
    __syncthreads();

    if (i < NN) {
        int excl = s_prefix + incl - v;
        g_rowptr[i] = excl;
        g_cursor[i] = excl;
        g_dsinv[i]  = rsqrtf((float)(v + 1));
        g_deg[i]    = 0;
        if (i == NN - 1) g_rowptr[NN] = s_prefix + incl;
    }
}

// ---------------- scatter: fill CSR adjacency ----------------
__global__ __launch_bounds__(256) void scatter_kernel(const void* __restrict__ ei, int E) {
    int is64 = block_detect_i64(ei);
    int e = blockIdx.x * 256 + threadIdx.x;
    if (e < E) {
        int s, d;
        if (is64) {
            s = (int)((const long long*)ei)[e];
            d = (int)((const long long*)ei)[(long long)E + e];
        } else {
            s = ((const int*)ei)[e];
            d = ((const int*)ei)[(long long)E + e];
        }
        if ((unsigned)d < (unsigned)NN && (unsigned)s < (unsigned)NN) {
            int p = atomicAdd(&g_cursor[d], 1);
            if ((unsigned)p < (unsigned)MAXE) g_esrc[p] = s;
        }
    }
}

// ---------------- tensor-core GEMM: g = (A @ W) * dsinv[row], tf32 3-pass split ----------------
// block: 256 thr (8 warps, 4m x 2n), tile 128 rows x 64 cols. k=64 in 8 steps of 8.
// C = Ah*Wh + Ah*Wl + Al*Wh  (lo*lo dropped; rel err ~1e-6)
#define GSTRIDE 68
#define GEMM_SMEM_BYTES ((128 * GSTRIDE + 2 * 64 * GSTRIDE) * 4)

__device__ __forceinline__ unsigned f2tf32(float a) {
    unsigned r;
    asm("cvt.rna.tf32.f32 %0, %1;" : "=r"(r) : "f"(a));
    return r;
}

__device__ __forceinline__ void mma_tf32(float* c, unsigned a0, unsigned a1,
                                         unsigned a2, unsigned a3,
                                         unsigned b0, unsigned b1) {
    asm volatile(
        "mma.sync.aligned.m16n8k8.row.col.f32.tf32.tf32.f32 "
        "{%0,%1,%2,%3}, {%4,%5,%6,%7}, {%8,%9}, {%0,%1,%2,%3};"
        : "+f"(c[0]), "+f"(c[1]), "+f"(c[2]), "+f"(c[3])
        : "r"(a0), "r"(a1), "r"(a2), "r"(a3), "r"(b0), "r"(b1));
}

__global__ __launch_bounds__(256) void gemm_mma_kernel(const float* __restrict__ Ain,
                                                       const float* __restrict__ W,
                                                       int use_hbuf) {
    extern __shared__ float smem[];
    float* sA  = smem;                       // [128][GSTRIDE] fp32
    float* sWh = smem + 128 * GSTRIDE;       // [n][GSTRIDE] (transposed W, tf32-hi as float)
    float* sWl = sWh + 64 * GSTRIDE;         // [n][GSTRIDE] (tf32-lo as float)
    const float* A = use_hbuf ? g_hbuf : Ain;

    int t = threadIdx.x;
    int row0 = blockIdx.x * 128;

    // W split (once per block): W is [k][n] row-major; store transposed [n][k]
    for (int e = t; e < 4096; e += 256) {
        int k = e >> 6, n = e & 63;
        float w = W[e];
        unsigned hi = f2tf32(w);
        float lof = w - __uint_as_float(hi);
        sWh[n * GSTRIDE + k] = __uint_as_float(hi);
        sWl[n * GSTRIDE + k] = __uint_as_float(f2tf32(lof));
    }
    // A tile load (fp32, stride 68; zero-fill out of range)
#pragma unroll
    for (int i = 0; i < 8; i++) {
        int q = t + i * 256;            // float4 index 0..2047
        int r = q >> 4;
        int c4 = (q & 15) << 2;
        float4 v = make_float4(0.f, 0.f, 0.f, 0.f);
        int grow = row0 + r;
        if (grow < NN) v = *(const float4*)(A + grow * 64 + c4);
        *(float4*)(sA + r * GSTRIDE + c4) = v;
    }
    __syncthreads();

    int w8 = t >> 5;                  // warp 0..7
    int mw = w8 >> 1, nw = w8 & 1;    // 4m x 2n
    int mo = mw * 32, no = nw * 32;
    int lane = t & 31;
    int g = lane >> 2, tg = lane & 3;

    float acc[2][4][4];
#pragma unroll
    for (int i = 0; i < 2; i++)
#pragma unroll
        for (int j = 0; j < 4; j++)
#pragma unroll
            for (int c = 0; c < 4; c++) acc[i][j][c] = 0.f;

#pragma unroll
    for (int ks = 0; ks < 8; ks++) {
        int k0 = ks * 8;
        // A fragments (2 mtiles), split hi/lo on the fly
        unsigned ah[2][4], al[2][4];
#pragma unroll
        for (int i = 0; i < 2; i++) {
            int r0 = (mo + 16 * i + g) * GSTRIDE;
            int r1 = r0 + 8 * GSTRIDE;
            float a0 = sA[r0 + k0 + tg];
            float a1 = sA[r1 + k0 + tg];
            float a2 = sA[r0 + k0 + tg + 4];
            float a3 = sA[r1 + k0 + tg + 4];
            ah[i][0] = f2tf32(a0); al[i][0] = f2tf32(a0 - __uint_as_float(ah[i][0]));
            ah[i][1] = f2tf32(a1); al[i][1] = f2tf32(a1 - __uint_as_float(ah[i][1]));
            ah[i][2] = f2tf32(a2); al[i][2] = f2tf32(a2 - __uint_as_float(ah[i][2]));
            ah[i][3] = f2tf32(a3); al[i][3] = f2tf32(a3 - __uint_as_float(ah[i][3]));
        }
        // B fragments (4 ntiles) hi/lo from transposed smem: col-major k8n8
#pragma unroll
        for (int j = 0; j < 4; j++) {
            int cbase = (no + 8 * j + g) * GSTRIDE + k0 + tg;
            unsigned bh0 = __float_as_uint(sWh[cbase]);
            unsigned bh1 = __float_as_uint(sWh[cbase + 4]);
            unsigned bl0 = __float_as_uint(sWl[cbase]);
            unsigned bl1 = __float_as_uint(sWl[cbase + 4]);
#pragma unroll
            for (int i = 0; i < 2; i++) {
                mma_tf32(acc[i][j], ah[i][0], ah[i][1], ah[i][2], ah[i][3], bh0, bh1);
                mma_tf32(acc[i][j], ah[i][0], ah[i][1], ah[i][2], ah[i][3], bl0, bl1);
                mma_tf32(acc[i][j], al[i][0], al[i][1], al[i][2], al[i][3], bh0, bh1);
            }
        }
    }

    // epilogue: scale by dsinv[row], write g_feat
#pragma unroll
    for (int i = 0; i < 2; i++) {
        int r0 = row0 + mo + 16 * i + g;
        int r1 = r0 + 8;
        float s0 = (r0 < NN) ? g_dsinv[r0] : 0.f;
        float s1 = (r1 < NN) ? g_dsinv[r1] : 0.f;
#pragma unroll
        for (int j = 0; j < 4; j++) {
            int col = no + 8 * j + 2 * tg;
            if (r0 < NN)
                *(float2*)(g_feat + r0 * 64 + col) =
                    make_float2(acc[i][j][0] * s0, acc[i][j][1] * s0);
            if (r1 < NN)
                *(float2*)(g_feat + r1 * 64 + col) =
                    make_float2(acc[i][j][2] * s1, acc[i][j][3] * s1);
        }
    }
}

// ---------------- aggregation: one warp per node, CSR gather, 8-deep MLP ----------------
__global__ __launch_bounds__(256) void aggregate_kernel(const float* __restrict__ bias,
                                                        float* __restrict__ dout,
                                                        int mode) {
    int warp = (blockIdx.x * blockDim.x + threadIdx.x) >> 5;
    int lane = threadIdx.x & 31;
    if (warp >= NN) return;
    int node = warp;
    int beg = g_rowptr[node];
    int end = g_rowptr[node + 1];

    const float2* __restrict__ Gv = (const float2*)g_feat;
    int off = node * 32 + lane;
    float2 s0v = Gv[off];
    float ax = s0v.x, ay = s0v.y;

    const unsigned full = 0xffffffffu;
    for (int base = beg; base < end; base += 32) {
        int idx = base + lane;
        int mysrc = (idx < end) ? g_esrc[idx] : 0;
        int cnt = min(32, end - base);
        int i = 0;
        for (; i + 8 <= cnt; i += 8) {
            int s0 = __shfl_sync(full, mysrc, i);
            int s1 = __shfl_sync(full, mysrc, i + 1);
            int s2 = __shfl_sync(full, mysrc, i + 2);
            int s3 = __shfl_sync(full, mysrc, i + 3);
            int s4 = __shfl_sync(full, mysrc, i + 4);
            int s5 = __shfl_sync(full, mysrc, i + 5);
            int s6 = __shfl_sync(full, mysrc, i + 6);
            int s7 = __shfl_sync(full, mysrc, i + 7);
            float2 v0 = Gv[s0 * 32 + lane];
            float2 v1 = Gv[s1 * 32 + lane];
            float2 v2 = Gv[s2 * 32 + lane];
            float2 v3 = Gv[s3 * 32 + lane];
            float2 v4 = Gv[s4 * 32 + lane];
            float2 v5 = Gv[s5 * 32 + lane];
            float2 v6 = Gv[s6 * 32 + lane];
            float2 v7 = Gv[s7 * 32 + lane];
            ax += v0.x; ay += v0.y; ax += v1.x; ay += v1.y;
            ax += v2.x; ay += v2.y; ax += v3.x; ay += v3.y;
            ax += v4.x; ay += v4.y; ax += v5.x; ay += v5.y;
            ax += v6.x; ay += v6.y; ax += v7.x; ay += v7.y;
        }
        for (; i < cnt; i++) {
            int s = __shfl_sync(full, mysrc, i);
            float2 v = Gv[s * 32 + lane];
            ax += v.x; ay += v.y;
        }
    }

    float ds = g_dsinv[node];
    float o0 = fmaf(ds, ax, bias[lane * 2]);
    float o1 = fmaf(ds, ay, bias[lane * 2 + 1]);
    float2* outv;
    if (mode < 2) {
        o0 = fmaxf(o0, 0.f);
        o1 = fmaxf(o1, 0.f);
        outv = (float2*)g_hbuf;
    } else {
        outv = (float2*)dout;
    }
    outv[off] = make_float2(o0, o1);
}

// ---------------- launch ----------------
extern "C" void kernel_launch(void* const* d_in, const int* in_sizes, int n_in,
                              void* d_out, int out_size) {
    const float* x  = (const float*)d_in[0];
    const void*  ei = d_in[1];
    const float* W0 = (const float*)d_in[2];
    const float* b0 = (const float*)d_in[3];
    const float* W1 = (const float*)d_in[4];
    const float* b1 = (const float*)d_in[5];
    const float* W2 = (const float*)d_in[6];
    const float* b2 = (const float*)d_in[7];
    float* out = (float*)d_out;

    int E = in_sizes[1] / 2;

    static int smem_set = 0;
    if (!smem_set) {
        cudaFuncSetAttribute(gemm_mma_kernel,
                             cudaFuncAttributeMaxDynamicSharedMemorySize,
                             GEMM_SMEM_BYTES);
        smem_set = 1;
    }

    hist_kernel<<<(E + 255) / 256, 256>>>(ei, E);
    scan_kernel<<<NB, 256>>>();
    scatter_kernel<<<(E + 255) / 256, 256>>>(ei, E);

    int gemm_blocks = (NN + 127) / 128;
    int agg_blocks  = (NN * 32 + 255) / 256;

    gemm_mma_kernel<<<gemm_blocks, 256, GEMM_SMEM_BYTES>>>(x, W0, 0);   // launch #4 → profiled
    aggregate_kernel<<<agg_blocks, 256>>>(b0, out, 0);
    gemm_mma_kernel<<<gemm_blocks, 256, GEMM_SMEM_BYTES>>>(x, W1, 1);
    aggregate_kernel<<<agg_blocks, 256>>>(b1, out, 1);
    gemm_mma_kernel<<<gemm_blocks, 256, GEMM_SMEM_BYTES>>>(x, W2, 1);
    aggregate_kernel<<<agg_blocks, 256>>>(b2, out, 2);
}